// round 3
// baseline (speedup 1.0000x reference)
#include <cuda_runtime.h>
#include <cuda_bf16.h>
#include <cstdint>

// Problem constants
// params: (64, 18378) fp32 ; batch: (128, 1, 28, 28) fp32 ; out: (64, 128, 10) fp32
// Param layout per init: w1[16*1*5*5]=400 @0, b1[16]@400, w2[32*16*5*5]=12800 @416,
// b2[32]@13216, wd[10*512]=5120 @13248, bd[10]@18368, total 18378.

#define NUM_INITS 64
#define BATCH_N   128
#define PSTRIDE   18378

// Scratch: act1[init][img][16][12][12]  (75.5 MB, static device array — allowed)
__device__ float g_act1[(size_t)NUM_INITS * BATCH_N * 16 * 12 * 12];

// ---------------------------------------------------------------------------
// Kernel 1: conv1 (1->16, 5x5 valid, 28->24) + bias + relu + maxpool2 -> 12x12
// One block per (init, image). 256 threads.
// Uses maxpool(relu(conv+b)) == relu(max(conv)+b) (monotonicity).
// ---------------------------------------------------------------------------
__global__ __launch_bounds__(256) void k1_conv1(
    const float* __restrict__ params, const float* __restrict__ batch)
{
    const int blk  = blockIdx.x;          // init*128 + img
    const int init = blk >> 7;
    const int img  = blk & 127;

    __shared__ float s_img[784];
    __shared__ float s_w[400];
    __shared__ float s_b[16];

    const float* p  = params + (size_t)init * PSTRIDE;
    const float* im = batch + (size_t)img * 784;

    for (int i = threadIdx.x; i < 784; i += 256) s_img[i] = im[i];
    for (int i = threadIdx.x; i < 400; i += 256) s_w[i]  = p[i];
    if (threadIdx.x < 16) s_b[threadIdx.x] = p[400 + threadIdx.x];
    __syncthreads();

    float* dst = g_act1 + (size_t)blk * 2304;

    for (int idx = threadIdx.x; idx < 2304; idx += 256) {
        const int c  = idx / 144;
        const int r  = idx - c * 144;
        const int ph = r / 12;
        const int pw = r - ph * 12;
        const float* w = s_w + c * 25;

        float best = -1e30f;
        #pragma unroll
        for (int dy = 0; dy < 2; dy++) {
            #pragma unroll
            for (int dx = 0; dx < 2; dx++) {
                const int y = 2 * ph + dy, x = 2 * pw + dx;
                float s = 0.f;
                #pragma unroll
                for (int ky = 0; ky < 5; ky++) {
                    const float* a = s_img + (y + ky) * 28 + x;
                    #pragma unroll
                    for (int kx = 0; kx < 5; kx++)
                        s = fmaf(a[kx], w[ky * 5 + kx], s);
                }
                best = fmaxf(best, s);
            }
        }
        dst[idx] = fmaxf(best + s_b[c], 0.f);
    }
}

// ---------------------------------------------------------------------------
// Kernel 2: conv2 (16->32, 5x5, 12->8) + bias + relu + pool -> (32,4,4)=512,
//           dense 512->10, log_softmax. One block per (init, image).
// 256 threads: thread = (oc, y) computes one conv-output row of 8 x-positions
// with a register-blocked sliding window (40 FMA per 17 LDS).
// ---------------------------------------------------------------------------
#define K2_SMEM_FLOATS (2304 + 12800 + 32 + 5120 + 16 + 1024 + 512 + 96)

__global__ __launch_bounds__(256) void k2_rest(
    const float* __restrict__ params, float* __restrict__ out)
{
    extern __shared__ float sm[];
    float* s_act  = sm;                 // 2304  (16,12,12)
    float* s_w2   = s_act + 2304;       // 12800 (32,16,5,5)
    float* s_b2   = s_w2 + 12800;       // 32
    float* s_wd   = s_b2 + 32;          // 5120  (10,512)
    float* s_bd   = s_wd + 5120;        // 16
    float* s_rm   = s_bd + 16;          // 1024  rowmax (32,8,4)
    float* s_pool = s_rm + 1024;        // 512
    float* s_red  = s_pool + 512;       // 96 (8 warps * 10 + 10 logits)

    const int blk  = blockIdx.x;
    const int init = blk >> 7;
    const int tid  = threadIdx.x;
    const float* p = params + (size_t)init * PSTRIDE;
    const float* src = g_act1 + (size_t)blk * 2304;

    for (int i = tid; i < 2304;  i += 256) s_act[i] = src[i];
    for (int i = tid; i < 12800; i += 256) s_w2[i]  = p[416 + i];
    if (tid < 32) s_b2[tid] = p[13216 + tid];
    for (int i = tid; i < 5120;  i += 256) s_wd[i]  = p[13248 + i];
    if (tid < 10) s_bd[tid] = p[18368 + tid];
    __syncthreads();

    // ---- conv2: thread (oc, y) computes s[0..7] over x ----
    {
        const int oc = tid >> 3;   // 0..31
        const int y  = tid & 7;    // 0..7
        float s[8];
        #pragma unroll
        for (int x = 0; x < 8; x++) s[x] = 0.f;

        const float* wbase = s_w2 + oc * 400;
        for (int ic = 0; ic < 16; ic++) {
            const float* arow = s_act + ic * 144;
            const float* wk   = wbase + ic * 25;
            #pragma unroll
            for (int ky = 0; ky < 5; ky++) {
                const float* a = arow + (y + ky) * 12;
                const float w0 = wk[ky * 5 + 0], w1 = wk[ky * 5 + 1],
                            w2 = wk[ky * 5 + 2], w3 = wk[ky * 5 + 3],
                            w4 = wk[ky * 5 + 4];
                float a0 = a[0], a1 = a[1], a2 = a[2], a3 = a[3];
                #pragma unroll
                for (int x = 0; x < 8; x++) {
                    const float a4 = a[x + 4];
                    s[x] = fmaf(a0, w0, s[x]);
                    s[x] = fmaf(a1, w1, s[x]);
                    s[x] = fmaf(a2, w2, s[x]);
                    s[x] = fmaf(a3, w3, s[x]);
                    s[x] = fmaf(a4, w4, s[x]);
                    a0 = a1; a1 = a2; a2 = a3; a3 = a4;
                }
            }
        }
        // horizontal pool (pairs along x)
        #pragma unroll
        for (int pw = 0; pw < 4; pw++)
            s_rm[(oc * 8 + y) * 4 + pw] = fmaxf(s[2 * pw], s[2 * pw + 1]);
    }
    __syncthreads();

    // ---- vertical pool + bias + relu -> s_pool[f], f = oc*16 + ph*4 + pw ----
    for (int f = tid; f < 512; f += 256) {
        const int oc = f >> 4, ph = (f >> 2) & 3, pw = f & 3;
        const float v = fmaxf(s_rm[(oc * 8 + 2 * ph) * 4 + pw],
                              s_rm[(oc * 8 + 2 * ph + 1) * 4 + pw]);
        s_pool[f] = fmaxf(v + s_b2[oc], 0.f);
    }
    __syncthreads();

    // ---- dense 512 -> 10 (block reduction, deterministic) ----
    float part[10];
    #pragma unroll
    for (int o = 0; o < 10; o++) part[o] = 0.f;
    for (int f = tid; f < 512; f += 256) {
        const float v = s_pool[f];
        #pragma unroll
        for (int o = 0; o < 10; o++)
            part[o] = fmaf(v, s_wd[o * 512 + f], part[o]);
    }
    #pragma unroll
    for (int off = 16; off > 0; off >>= 1) {
        #pragma unroll
        for (int o = 0; o < 10; o++)
            part[o] += __shfl_down_sync(0xffffffffu, part[o], off);
    }
    const int warp = tid >> 5, lane = tid & 31;
    if (lane == 0) {
        #pragma unroll
        for (int o = 0; o < 10; o++) s_red[warp * 10 + o] = part[o];
    }
    __syncthreads();
    if (tid < 10) {
        float s = s_bd[tid];
        #pragma unroll
        for (int w = 0; w < 8; w++) s += s_red[w * 10 + tid];
        s_red[80 + tid] = s;
    }
    __syncthreads();

    // ---- log_softmax over 10 classes ----
    if (tid == 0) {
        float mx = -1e30f;
        #pragma unroll
        for (int o = 0; o < 10; o++) mx = fmaxf(mx, s_red[80 + o]);
        float se = 0.f;
        #pragma unroll
        for (int o = 0; o < 10; o++) se += expf(s_red[80 + o] - mx);
        const float lse = mx + logf(se);
        float* od = out + (size_t)blk * 10;
        #pragma unroll
        for (int o = 0; o < 10; o++) od[o] = s_red[80 + o] - lse;
    }
}

// ---------------------------------------------------------------------------
extern "C" void kernel_launch(void* const* d_in, const int* in_sizes, int n_in,
                              void* d_out, int out_size)
{
    const float* params = (const float*)d_in[0];
    const float* batch  = (const float*)d_in[1];
    // Defensive: metadata order should be (params, batch); swap if reversed.
    if (n_in >= 2 && in_sizes[0] == BATCH_N * 784 &&
        in_sizes[1] == NUM_INITS * PSTRIDE) {
        const float* t = params; params = batch; batch = t;
    }
    float* out = (float*)d_out;

    // Idempotent; safe to call every launch (no static state per harness rules).
    cudaFuncSetAttribute(k2_rest, cudaFuncAttributeMaxDynamicSharedMemorySize,
                         K2_SMEM_FLOATS * sizeof(float));

    const int grid = NUM_INITS * BATCH_N;  // 8192
    k1_conv1<<<grid, 256>>>(params, batch);
    k2_rest<<<grid, 256, K2_SMEM_FLOATS * sizeof(float)>>>(params, out);
}

// round 6
// speedup vs baseline: 1.3660x; 1.3660x over previous
#include <cuda_runtime.h>
#include <cuda_bf16.h>
#include <cstdint>

#define NUM_INITS 64
#define BATCH_N   128
#define PSTRIDE   18378

// act1[init][img][16][12][12]  (75.5 MB scratch)
__device__ float g_act1[(size_t)NUM_INITS * BATCH_N * 16 * 12 * 12];

// ---------------------------------------------------------------------------
// Kernel 1: conv1 (1->16, 5x5, 28->24) + bias + relu + maxpool2 -> 12x12
// One block per (init, image). 256 threads.
// ---------------------------------------------------------------------------
__global__ __launch_bounds__(256) void k1_conv1(
    const float* __restrict__ params, const float* __restrict__ batch)
{
    const int blk  = blockIdx.x;
    const int init = blk >> 7;
    const int img  = blk & 127;

    __shared__ float s_img[784];
    __shared__ float s_w[400];
    __shared__ float s_b[16];

    const float* p  = params + (size_t)init * PSTRIDE;
    const float* im = batch + (size_t)img * 784;

    for (int i = threadIdx.x; i < 784; i += 256) s_img[i] = im[i];
    for (int i = threadIdx.x; i < 400; i += 256) s_w[i]  = p[i];
    if (threadIdx.x < 16) s_b[threadIdx.x] = p[400 + threadIdx.x];
    __syncthreads();

    float* dst = g_act1 + (size_t)blk * 2304;

    for (int idx = threadIdx.x; idx < 2304; idx += 256) {
        const int c  = idx / 144;
        const int r  = idx - c * 144;
        const int ph = r / 12;
        const int pw = r - ph * 12;
        const float* w = s_w + c * 25;

        float best = -1e30f;
        #pragma unroll
        for (int dy = 0; dy < 2; dy++) {
            #pragma unroll
            for (int dx = 0; dx < 2; dx++) {
                const int y = 2 * ph + dy, x = 2 * pw + dx;
                float s = 0.f;
                #pragma unroll
                for (int ky = 0; ky < 5; ky++) {
                    const float* a = s_img + (y + ky) * 28 + x;
                    #pragma unroll
                    for (int kx = 0; kx < 5; kx++)
                        s = fmaf(a[kx], w[ky * 5 + kx], s);
                }
                best = fmaxf(best, s);
            }
        }
        dst[idx] = fmaxf(best + s_b[c], 0.f);
    }
}

// ---------------------------------------------------------------------------
// Kernel 2: conv2 + pool + dense + log_softmax, TWO images per block.
// 256 threads = 2 img halves x 128. Conv thread = (img, oc-pair, y):
// 2 oc x 8 x = 16 accumulators; per (ic,ky): 80 FMA vs 22 conflict-free LDS.
// w2 smem padded to stride 404 per oc (bank-conflict-free weight loads).
// ---------------------------------------------------------------------------
#define W2_STRIDE 404
#define K2_SMEM_FLOATS (4608 + 32*W2_STRIDE + 32 + 5120 + 16 + 2048 + 1024 + 128)

__global__ __launch_bounds__(256) void k2_rest(
    const float* __restrict__ params, float* __restrict__ out)
{
    extern __shared__ float sm[];
    float* s_act  = sm;                       // 4608  (2 img x 16x12x12)
    float* s_w2   = s_act + 4608;             // 32*404 padded (32,16,5,5)
    float* s_b2   = s_w2 + 32 * W2_STRIDE;    // 32
    float* s_wd   = s_b2 + 32;                // 5120  (10,512)
    float* s_bd   = s_wd + 5120;              // 16
    float* s_rm   = s_bd + 16;                // 2048  rowmax (2,32,8,4)
    float* s_pool = s_rm + 2048;              // 1024  (2,512)
    float* s_red  = s_pool + 1024;            // 128   (2 x 64)

    const int tid  = threadIdx.x;
    const int init = blockIdx.x >> 6;
    const int pair = blockIdx.x & 63;         // images 2*pair, 2*pair+1
    const float* p = params + (size_t)init * PSTRIDE;

    // ---- stage smem ----
    {
        const float* src = g_act1 + ((size_t)(init * 128 + pair * 2)) * 2304;
        for (int i = tid; i < 4608; i += 256) s_act[i] = src[i];
        for (int i = tid; i < 12800; i += 256) {
            const int oc = i / 400;
            s_w2[oc * W2_STRIDE + (i - oc * 400)] = p[416 + i];
        }
        if (tid < 32) s_b2[tid] = p[13216 + tid];
        for (int i = tid; i < 5120; i += 256) s_wd[i] = p[13248 + i];
        if (tid < 10) s_bd[tid] = p[18368 + tid];
    }
    __syncthreads();

    const int img = tid >> 7;        // 0/1 (also fixed per warp)
    const int r   = tid & 127;

    // ---- conv2: thread = (img, oc-pair og, y); 2 oc x 8 x accumulators ----
    {
        const int og = r >> 3;       // 0..15 -> oc = 2*og, 2*og+1
        const int y  = r & 7;

        float s0[8], s1[8];
        #pragma unroll
        for (int x = 0; x < 8; x++) { s0[x] = 0.f; s1[x] = 0.f; }

        const float* actb = s_act + img * 2304;
        const float* wa_b = s_w2 + (2 * og) * W2_STRIDE;
        const float* wb_b = wa_b + W2_STRIDE;

        for (int ic = 0; ic < 16; ic++) {
            const float* arow = actb + ic * 144;
            const float* wka  = wa_b + ic * 25;
            const float* wkb  = wb_b + ic * 25;
            #pragma unroll
            for (int ky = 0; ky < 5; ky++) {
                const float* a = arow + (y + ky) * 12;
                const float wa0 = wka[ky*5+0], wa1 = wka[ky*5+1], wa2 = wka[ky*5+2],
                            wa3 = wka[ky*5+3], wa4 = wka[ky*5+4];
                const float wb0 = wkb[ky*5+0], wb1 = wkb[ky*5+1], wb2 = wkb[ky*5+2],
                            wb3 = wkb[ky*5+3], wb4 = wkb[ky*5+4];
                float a0 = a[0], a1 = a[1], a2 = a[2], a3 = a[3];
                #pragma unroll
                for (int x = 0; x < 8; x++) {
                    const float a4 = a[x + 4];
                    s0[x] = fmaf(a0, wa0, s0[x]);
                    s0[x] = fmaf(a1, wa1, s0[x]);
                    s0[x] = fmaf(a2, wa2, s0[x]);
                    s0[x] = fmaf(a3, wa3, s0[x]);
                    s0[x] = fmaf(a4, wa4, s0[x]);
                    s1[x] = fmaf(a0, wb0, s1[x]);
                    s1[x] = fmaf(a1, wb1, s1[x]);
                    s1[x] = fmaf(a2, wb2, s1[x]);
                    s1[x] = fmaf(a3, wb3, s1[x]);
                    s1[x] = fmaf(a4, wb4, s1[x]);
                    a0 = a1; a1 = a2; a2 = a3; a3 = a4;
                }
            }
        }
        // horizontal pool pairs along x -> rowmax (img, oc, y, 4)
        float* rm = s_rm + img * 1024;
        #pragma unroll
        for (int pw = 0; pw < 4; pw++) {
            rm[((2*og)   * 8 + y) * 4 + pw] = fmaxf(s0[2*pw], s0[2*pw+1]);
            rm[((2*og+1) * 8 + y) * 4 + pw] = fmaxf(s1[2*pw], s1[2*pw+1]);
        }
    }
    __syncthreads();

    // ---- vertical pool + bias + relu -> s_pool[img][f] ----
    for (int idx = tid; idx < 1024; idx += 256) {
        const int im2 = idx >> 9;
        const int f   = idx & 511;
        const int oc = f >> 4, ph = (f >> 2) & 3, pw = f & 3;
        const float* rm = s_rm + im2 * 1024;
        const float v = fmaxf(rm[(oc*8 + 2*ph) * 4 + pw],
                              rm[(oc*8 + 2*ph + 1) * 4 + pw]);
        s_pool[im2 * 512 + f] = fmaxf(v + s_b2[oc], 0.f);
    }
    __syncthreads();

    // ---- dense 512->10: 128 threads per image, 4 features each ----
    {
        float part[10];
        #pragma unroll
        for (int o = 0; o < 10; o++) part[o] = 0.f;
        const float* pool = s_pool + img * 512;
        #pragma unroll
        for (int it = 0; it < 4; it++) {
            const int f = r + it * 128;
            const float v = pool[f];
            #pragma unroll
            for (int o = 0; o < 10; o++)
                part[o] = fmaf(v, s_wd[o * 512 + f], part[o]);
        }
        #pragma unroll
        for (int off = 16; off > 0; off >>= 1) {
            #pragma unroll
            for (int o = 0; o < 10; o++)
                part[o] += __shfl_down_sync(0xffffffffu, part[o], off);
        }
        const int lane = tid & 31;
        const int wimg = r >> 5;      // warp index within image half (0..3)
        if (lane == 0) {
            #pragma unroll
            for (int o = 0; o < 10; o++)
                s_red[img * 64 + wimg * 10 + o] = part[o];
        }
    }
    __syncthreads();

    if (r < 10) {
        const float* rd = s_red + img * 64;
        float s = s_bd[r] + rd[0 + r] + rd[10 + r] + rd[20 + r] + rd[30 + r];
        s_red[img * 64 + 40 + r] = s;
    }
    __syncthreads();

    // ---- log_softmax (one thread per image) ----
    if (r == 0) {
        const float* lg = s_red + img * 64 + 40;
        float mx = -1e30f;
        #pragma unroll
        for (int o = 0; o < 10; o++) mx = fmaxf(mx, lg[o]);
        float se = 0.f;
        #pragma unroll
        for (int o = 0; o < 10; o++) se += expf(lg[o] - mx);
        const float lse = mx + logf(se);
        float* od = out + ((size_t)init * 128 + pair * 2 + img) * 10;
        #pragma unroll
        for (int o = 0; o < 10; o++) od[o] = lg[o] - lse;
    }
}

// ---------------------------------------------------------------------------
extern "C" void kernel_launch(void* const* d_in, const int* in_sizes, int n_in,
                              void* d_out, int out_size)
{
    const float* params = (const float*)d_in[0];
    const float* batch  = (const float*)d_in[1];
    if (n_in >= 2 && in_sizes[0] == BATCH_N * 784 &&
        in_sizes[1] == NUM_INITS * PSTRIDE) {
        const float* t = params; params = batch; batch = t;
    }
    float* out = (float*)d_out;

    cudaFuncSetAttribute(k2_rest, cudaFuncAttributeMaxDynamicSharedMemorySize,
                         K2_SMEM_FLOATS * sizeof(float));

    k1_conv1<<<NUM_INITS * BATCH_N, 256>>>(params, batch);
    k2_rest<<<NUM_INITS * (BATCH_N / 2), 256,
              K2_SMEM_FLOATS * sizeof(float)>>>(params, out);
}

// round 15
// speedup vs baseline: 1.6110x; 1.1793x over previous
#include <cuda_runtime.h>
#include <cuda_bf16.h>
#include <cstdint>

#define NUM_INITS 64
#define BATCH_N   128
#define PSTRIDE   18378

typedef unsigned long long ull;

__device__ __forceinline__ ull pack_dup(float v) {
    ull r; asm("mov.b64 %0, {%1, %1};" : "=l"(r) : "f"(v)); return r;
}
__device__ __forceinline__ void fma2(ull& d, ull a, ull b) {
    asm("fma.rn.f32x2 %0, %1, %2, %3;" : "=l"(d) : "l"(a), "l"(b), "l"(d));
}

// act1[init][img][16][12][12]  (75.5 MB scratch)
__device__ float g_act1[(size_t)NUM_INITS * BATCH_N * 16 * 12 * 12];

// ---------------------------------------------------------------------------
// Kernel 1: conv1 (1->16, 5x5, 28->24) + bias + relu + maxpool2 -> 12x12
// ---------------------------------------------------------------------------
__global__ __launch_bounds__(256) void k1_conv1(
    const float* __restrict__ params, const float* __restrict__ batch)
{
    const int blk  = blockIdx.x;
    const int init = blk >> 7;
    const int img  = blk & 127;

    __shared__ float s_img[784];
    __shared__ float s_w[400];
    __shared__ float s_b[16];

    const float* p  = params + (size_t)init * PSTRIDE;
    const float* im = batch + (size_t)img * 784;

    for (int i = threadIdx.x; i < 784; i += 256) s_img[i] = im[i];
    for (int i = threadIdx.x; i < 400; i += 256) s_w[i]  = p[i];
    if (threadIdx.x < 16) s_b[threadIdx.x] = p[400 + threadIdx.x];
    __syncthreads();

    float* dst = g_act1 + (size_t)blk * 2304;

    for (int idx = threadIdx.x; idx < 2304; idx += 256) {
        const int c  = idx / 144;
        const int r  = idx - c * 144;
        const int ph = r / 12;
        const int pw = r - ph * 12;
        const float* w = s_w + c * 25;

        float best = -1e30f;
        #pragma unroll
        for (int dy = 0; dy < 2; dy++) {
            #pragma unroll
            for (int dx = 0; dx < 2; dx++) {
                const int y = 2 * ph + dy, x = 2 * pw + dx;
                float s = 0.f;
                #pragma unroll
                for (int ky = 0; ky < 5; ky++) {
                    const float* a = s_img + (y + ky) * 28 + x;
                    #pragma unroll
                    for (int kx = 0; kx < 5; kx++)
                        s = fmaf(a[kx], w[ky * 5 + kx], s);
                }
                best = fmaxf(best, s);
            }
        }
        dst[idx] = fmaxf(best + s_b[c], 0.f);
    }
}

// ---------------------------------------------------------------------------
// Kernel 2: conv2 + pool + dense + log_softmax, 2 images/block.
// Conv uses packed fp32x2 FMA (FFMA2): accumulator pair = (oc 2g, oc 2g+1),
// weights staged interleaved (pair-adjacent) so one LDS.64 loads both.
// Interleaved weight stride 802 floats: bank-staggered + 8B-aligned.
// ---------------------------------------------------------------------------
#define W2P_STRIDE 802
#define K2_SMEM_FLOATS (4608 + 16*W2P_STRIDE + 32 + 5120 + 16 + 2048 + 1024 + 128)

__global__ __launch_bounds__(256) void k2_rest(
    const float* __restrict__ params, float* __restrict__ out)
{
    extern __shared__ float sm[];
    float* s_act  = sm;                        // 4608  (2 img x 16x12x12)
    float* s_w2p  = s_act + 4608;              // 16*802 interleaved oc-pairs
    float* s_b2   = s_w2p + 16 * W2P_STRIDE;   // 32
    float* s_wd   = s_b2 + 32;                 // 5120  (10,512)
    float* s_bd   = s_wd + 5120;               // 16
    float* s_rm   = s_bd + 16;                 // 2048  rowmax (2,32,8,4)
    float* s_pool = s_rm + 2048;               // 1024  (2,512)
    float* s_red  = s_pool + 1024;             // 128   (2 x 64)

    const int tid  = threadIdx.x;
    const int init = blockIdx.x >> 6;
    const int pair = blockIdx.x & 63;          // images 2*pair, 2*pair+1
    const float* p = params + (size_t)init * PSTRIDE;

    // ---- stage smem ----
    {
        const float* src = g_act1 + ((size_t)(init * 128 + pair * 2)) * 2304;
        for (int i = tid; i < 4608; i += 256) s_act[i] = src[i];
        for (int i = tid; i < 12800; i += 256) {
            const int oc = i / 400;
            const int j  = i - oc * 400;
            s_w2p[(oc >> 1) * W2P_STRIDE + 2 * j + (oc & 1)] = p[416 + i];
        }
        if (tid < 32) s_b2[tid] = p[13216 + tid];
        for (int i = tid; i < 5120; i += 256) s_wd[i] = p[13248 + i];
        if (tid < 10) s_bd[tid] = p[18368 + tid];
    }
    __syncthreads();

    const int img = tid >> 7;        // 0/1 (fixed per warp)
    const int r   = tid & 127;

    // ---- conv2: thread = (img, oc-pair og, y); packed 2-oc x 8-x accs ----
    {
        const int og = r >> 3;       // 0..15 -> oc = 2*og, 2*og+1
        const int y  = r & 7;

        ull acc[8];
        #pragma unroll
        for (int x = 0; x < 8; x++) acc[x] = 0ull;   // (0.0f, 0.0f)

        const float* actb = s_act + img * 2304;
        const float* wgp  = s_w2p + og * W2P_STRIDE;

        for (int ic = 0; ic < 16; ic++) {
            const float* arow = actb + ic * 144;
            const ull* wkp = (const ull*)(wgp + ic * 50);
            #pragma unroll
            for (int ky = 0; ky < 5; ky++) {
                const float* a = arow + (y + ky) * 12;
                const ull w0 = wkp[ky*5+0], w1 = wkp[ky*5+1], w2 = wkp[ky*5+2],
                          w3 = wkp[ky*5+3], w4 = wkp[ky*5+4];
                ull p0 = pack_dup(a[0]), p1 = pack_dup(a[1]),
                    p2 = pack_dup(a[2]), p3 = pack_dup(a[3]);
                #pragma unroll
                for (int x = 0; x < 8; x++) {
                    const ull p4 = pack_dup(a[x + 4]);
                    fma2(acc[x], p0, w0);
                    fma2(acc[x], p1, w1);
                    fma2(acc[x], p2, w2);
                    fma2(acc[x], p3, w3);
                    fma2(acc[x], p4, w4);
                    p0 = p1; p1 = p2; p2 = p3; p3 = p4;
                }
            }
        }
        // unpack + horizontal pool pairs along x -> rowmax (img, oc, y, 4)
        float* rm = s_rm + img * 1024;
        #pragma unroll
        for (int pw = 0; pw < 4; pw++) {
            float l0, h0, l1, h1;
            asm("mov.b64 {%0, %1}, %2;" : "=f"(l0), "=f"(h0) : "l"(acc[2*pw]));
            asm("mov.b64 {%0, %1}, %2;" : "=f"(l1), "=f"(h1) : "l"(acc[2*pw+1]));
            rm[((2*og)   * 8 + y) * 4 + pw] = fmaxf(l0, l1);
            rm[((2*og+1) * 8 + y) * 4 + pw] = fmaxf(h0, h1);
        }
    }
    __syncthreads();

    // ---- vertical pool + bias + relu -> s_pool[img][f] ----
    for (int idx = tid; idx < 1024; idx += 256) {
        const int im2 = idx >> 9;
        const int f   = idx & 511;
        const int oc = f >> 4, ph = (f >> 2) & 3, pw = f & 3;
        const float* rm = s_rm + im2 * 1024;
        const float v = fmaxf(rm[(oc*8 + 2*ph) * 4 + pw],
                              rm[(oc*8 + 2*ph + 1) * 4 + pw]);
        s_pool[im2 * 512 + f] = fmaxf(v + s_b2[oc], 0.f);
    }
    __syncthreads();

    // ---- dense 512->10: 128 threads per image, 4 features each ----
    {
        float part[10];
        #pragma unroll
        for (int o = 0; o < 10; o++) part[o] = 0.f;
        const float* pool = s_pool + img * 512;
        #pragma unroll
        for (int it = 0; it < 4; it++) {
            const int f = r + it * 128;
            const float v = pool[f];
            #pragma unroll
            for (int o = 0; o < 10; o++)
                part[o] = fmaf(v, s_wd[o * 512 + f], part[o]);
        }
        #pragma unroll
        for (int off = 16; off > 0; off >>= 1) {
            #pragma unroll
            for (int o = 0; o < 10; o++)
                part[o] += __shfl_down_sync(0xffffffffu, part[o], off);
        }
        const int lane = tid & 31;
        const int wimg = r >> 5;
        if (lane == 0) {
            #pragma unroll
            for (int o = 0; o < 10; o++)
                s_red[img * 64 + wimg * 10 + o] = part[o];
        }
    }
    __syncthreads();

    if (r < 10) {
        const float* rd = s_red + img * 64;
        float s = s_bd[r] + rd[0 + r] + rd[10 + r] + rd[20 + r] + rd[30 + r];
        s_red[img * 64 + 40 + r] = s;
    }
    __syncthreads();

    // ---- log_softmax (one thread per image) ----
    if (r == 0) {
        const float* lg = s_red + img * 64 + 40;
        float mx = -1e30f;
        #pragma unroll
        for (int o = 0; o < 10; o++) mx = fmaxf(mx, lg[o]);
        float se = 0.f;
        #pragma unroll
        for (int o = 0; o < 10; o++) se += expf(lg[o] - mx);
        const float lse = mx + logf(se);
        float* od = out + ((size_t)init * 128 + pair * 2 + img) * 10;
        #pragma unroll
        for (int o = 0; o < 10; o++) od[o] = lg[o] - lse;
    }
}

// ---------------------------------------------------------------------------
extern "C" void kernel_launch(void* const* d_in, const int* in_sizes, int n_in,
                              void* d_out, int out_size)
{
    const float* params = (const float*)d_in[0];
    const float* batch  = (const float*)d_in[1];
    if (n_in >= 2 && in_sizes[0] == BATCH_N * 784 &&
        in_sizes[1] == NUM_INITS * PSTRIDE) {
        const float* t = params; params = batch; batch = t;
    }
    float* out = (float*)d_out;

    cudaFuncSetAttribute(k2_rest, cudaFuncAttributeMaxDynamicSharedMemorySize,
                         K2_SMEM_FLOATS * sizeof(float));

    k1_conv1<<<NUM_INITS * BATCH_N, 256>>>(params, batch);
    k2_rest<<<NUM_INITS * (BATCH_N / 2), 256,
              K2_SMEM_FLOATS * sizeof(float)>>>(params, out);
}